// round 2
// baseline (speedup 1.0000x reference)
#include <cuda_runtime.h>
#include <cstdint>

#define B 4
#define L 2048
#define H 8
#define D 64
#define NT 38           // n_top
#define SK 38           // sample_k
#define NIDX (L*SK)     // 77824

// ---------------- scratch (no allocations allowed) ----------------
__device__ int   g_idx[NIDX];     // index_sample, row-major (q, j)
__device__ float g_M[B*H*L];      // sparsity metric
__device__ int   g_top[B*H*NT];   // selected query indices per (b,h)

// ---------------- threefry2x32-20 (exact jax match) ----------------
__device__ __forceinline__ uint32_t rotl32(uint32_t x, int r) {
    return (x << r) | (x >> (32 - r));
}

__device__ __forceinline__ void threefry2x32(uint32_t k0, uint32_t k1,
                                             uint32_t x0, uint32_t x1,
                                             uint32_t& o0, uint32_t& o1) {
    uint32_t ks2 = k0 ^ k1 ^ 0x1BD11BDAu;
    x0 += k0; x1 += k1;
#define TF_R(R) { x0 += x1; x1 = rotl32(x1, (R)); x1 ^= x0; }
    TF_R(13) TF_R(15) TF_R(26) TF_R(6)
    x0 += k1;  x1 += ks2 + 1u;
    TF_R(17) TF_R(29) TF_R(16) TF_R(24)
    x0 += ks2; x1 += k0 + 2u;
    TF_R(13) TF_R(15) TF_R(26) TF_R(6)
    x0 += k0;  x1 += k1 + 3u;
    TF_R(17) TF_R(29) TF_R(16) TF_R(24)
    x0 += k1;  x1 += ks2 + 4u;
    TF_R(13) TF_R(15) TF_R(26) TF_R(6)
    x0 += ks2; x1 += k0 + 5u;
#undef TF_R
    o0 = x0; o1 = x1;
}

// jax threefry_partitionable=True (default since 0.4.36) semantics:
//   split(key=(0,42)) foldlike: k_i = threefry2x32(key, hi=0, lo=i) -> (y0, y1)
//   lower_key = k2 = threefry2x32((0,42), 0, 1)
//   random_bits(k2, 32, shape): element t uses 64-bit counter t (hi=0, lo=t);
//   bits[t] = y0 ^ y1
//   randint span=2048 (pow2): multiplier = 0 -> index = bits & 2047
__global__ void k_genidx() {
    int t = blockIdx.x * blockDim.x + threadIdx.x;
    if (t >= NIDX) return;
    uint32_t c0, c1;
    threefry2x32(0u, 42u, 0u, 1u, c0, c1);   // lower key (constant-folds)
    uint32_t o0, o1;
    threefry2x32(c0, c1, 0u, (uint32_t)t, o0, o1);
    g_idx[t] = (int)((o0 ^ o1) & (uint32_t)(L - 1));
}

// ---------------- M metric: warp per query ----------------
// M[bh,q] = max_j dot(Q[q], K[idx[q,j]]) - (sum_j dot) / L
__global__ void k_M(const float* __restrict__ Q, const float* __restrict__ K) {
    int bh = blockIdx.x;
    int b = bh >> 3, h = bh & 7;
    int w = threadIdx.x >> 5, l = threadIdx.x & 31;
    int q = blockIdx.y * 8 + w;

    const float2* qr = (const float2*)(Q + (((size_t)b * L + q) * H + h) * D);
    float2 qv = qr[l];

    float mx = -1e30f, sm = 0.f;
    const int* ip = &g_idx[q * SK];
    for (int j = 0; j < SK; j++) {
        int k = ip[j];
        const float2* kr = (const float2*)(K + (((size_t)b * L + k) * H + h) * D);
        float2 kv = kr[l];
        float p = qv.x * kv.x + qv.y * kv.y;
        #pragma unroll
        for (int o = 16; o; o >>= 1) p += __shfl_xor_sync(0xffffffffu, p, o);
        mx = fmaxf(mx, p);
        sm += p;
    }
    if (l == 0) g_M[bh * L + q] = mx - sm * (1.0f / (float)L);
}

// ---------------- top-38 per (b,h): iterated block argmax ----------------
__global__ void k_topk() {
    int bh = blockIdx.x;
    __shared__ float vals[L];
    __shared__ float rv[256];
    __shared__ int   ri[256];
    int tid = threadIdx.x;
    for (int i = tid; i < L; i += 256) vals[i] = g_M[bh * L + i];
    __syncthreads();
    for (int t = 0; t < NT; t++) {
        float bv = -1e38f; int bi = L;
        for (int i = tid; i < L; i += 256) {
            float v = vals[i];
            if (v > bv || (v == bv && i < bi)) { bv = v; bi = i; }
        }
        rv[tid] = bv; ri[tid] = bi;
        __syncthreads();
        for (int s = 128; s; s >>= 1) {
            if (tid < s) {
                float ov = rv[tid + s]; int oi = ri[tid + s];
                if (ov > rv[tid] || (ov == rv[tid] && oi < ri[tid])) {
                    rv[tid] = ov; ri[tid] = oi;
                }
            }
            __syncthreads();
        }
        if (tid == 0) { g_top[bh * NT + t] = ri[0]; vals[ri[0]] = -1e38f; }
        __syncthreads();
    }
}

// ---------------- cumsum(V) along L, per (b,h); writes ALL of d_out ----------------
// 512 threads: c = tid&63 (column d), g = tid>>6 (8 groups of 16 rows per 128-row tile)
__global__ void k_cumsum(const float* __restrict__ V, float* __restrict__ out) {
    int bh = blockIdx.x;
    int b = bh >> 3, h = bh & 7;
    __shared__ float tile[128 * 64];
    __shared__ float gsum[8 * 64];
    __shared__ float running[64];
    int tid = threadIdx.x;
    int c = tid & 63, g = tid >> 6;
    if (tid < 64) running[tid] = 0.f;
    __syncthreads();

    for (int r0 = 0; r0 < L; r0 += 128) {
        for (int i = tid; i < 128 * 64; i += 512) {
            int r = i >> 6, cc = i & 63;
            tile[i] = V[(((size_t)b * L + r0 + r) * H + h) * D + cc];
        }
        __syncthreads();

        float s = 0.f;
        int rbase = g * 16;
        #pragma unroll
        for (int r = 0; r < 16; r++) {
            s += tile[(rbase + r) * 64 + c];
            tile[(rbase + r) * 64 + c] = s;
        }
        gsum[g * 64 + c] = s;
        __syncthreads();

        float prefix = running[c];
        for (int gg = 0; gg < g; gg++) prefix += gsum[gg * 64 + c];
        __syncthreads();                       // all running[] reads done
        if (g == 7) running[c] = prefix + gsum[7 * 64 + c];

        #pragma unroll
        for (int r = 0; r < 16; r++) {
            out[(((size_t)b * L + r0 + rbase + r) * H + h) * D + c] =
                tile[(rbase + r) * 64 + c] + prefix;
        }
        __syncthreads();                       // protect tile/gsum/running for next iter
    }
}

// ---------------- causal attention for selected queries ----------------
// One block per selected query; 8 warps stride keys k in [0, q]; online softmax;
// lane owns float2 of the D dim; 8-warp flash-merge at the end.
__global__ void k_attn(const float* __restrict__ Q, const float* __restrict__ K,
                       const float* __restrict__ V, float* __restrict__ out) {
    int u = blockIdx.x;
    int bh = u / NT, s = u % NT;
    int b = bh >> 3, h = bh & 7;
    int q = g_top[bh * NT + s];
    int w = threadIdx.x >> 5, l = threadIdx.x & 31;
    const float scale = 0.125f;  // 1/sqrt(64)

    const float2* qr = (const float2*)(Q + (((size_t)b * L + q) * H + h) * D);
    float2 qv = qr[l];

    float m = -1e30f, lsum = 0.f;
    float2 acc = make_float2(0.f, 0.f);
    for (int k = w; k <= q; k += 8) {
        const float2* kr = (const float2*)(K + (((size_t)b * L + k) * H + h) * D);
        float2 kv = kr[l];
        float p = qv.x * kv.x + qv.y * kv.y;
        #pragma unroll
        for (int o = 16; o; o >>= 1) p += __shfl_xor_sync(0xffffffffu, p, o);
        float sc = p * scale;
        float mn = fmaxf(m, sc);
        float alpha = __expf(m - mn);
        float pe    = __expf(sc - mn);
        const float2* vr = (const float2*)(V + (((size_t)b * L + k) * H + h) * D);
        float2 vv = vr[l];
        lsum  = lsum * alpha + pe;
        acc.x = acc.x * alpha + pe * vv.x;
        acc.y = acc.y * alpha + pe * vv.y;
        m = mn;
    }

    __shared__ float sm_[8], sl_[8], sacc[8][64];
    if (l == 0) { sm_[w] = m; sl_[w] = lsum; }
    sacc[w][2 * l]     = acc.x;
    sacc[w][2 * l + 1] = acc.y;
    __syncthreads();

    if (threadIdx.x < 64) {
        int d = threadIdx.x;
        float gm = -1e30f;
        for (int ww = 0; ww < 8; ww++)
            if (sl_[ww] > 0.f) gm = fmaxf(gm, sm_[ww]);
        float den = 0.f, num = 0.f;
        for (int ww = 0; ww < 8; ww++) {
            if (sl_[ww] > 0.f) {
                float f = __expf(sm_[ww] - gm);
                den += f * sl_[ww];
                num += f * sacc[ww][d];
            }
        }
        out[(((size_t)b * L + q) * H + h) * D + d] = num / den;
    }
}

// ---------------- launch ----------------
extern "C" void kernel_launch(void* const* d_in, const int* in_sizes, int n_in,
                              void* d_out, int out_size) {
    (void)in_sizes; (void)n_in; (void)out_size;
    const float* Q = (const float*)d_in[0];
    const float* K = (const float*)d_in[1];
    const float* V = (const float*)d_in[2];
    float* out = (float*)d_out;

    k_genidx<<<(NIDX + 255) / 256, 256>>>();
    k_M<<<dim3(B * H, L / 8), 256>>>(Q, K);
    k_topk<<<B * H, 256>>>();
    k_cumsum<<<B * H, 512>>>(V, out);
    k_attn<<<B * H * NT, 256>>>(Q, K, V, out);
}

// round 3
// speedup vs baseline: 1.8814x; 1.8814x over previous
#include <cuda_runtime.h>
#include <cstdint>

#define B 4
#define L 2048
#define H 8
#define D 64
#define NT 38           // n_top
#define SK 38           // sample_k
#define NIDX (L*SK)     // 77824
#define CH 16           // cumsum chunks
#define CROWS (L/CH)    // 128 rows per chunk

// ---------------- scratch (no allocations allowed) ----------------
__device__ int   g_idx[NIDX];          // index_sample, row-major (q, j)
__device__ float g_M[B*H*L];           // sparsity metric
__device__ int   g_top[B*H*NT];        // selected query indices per (b,h)
__device__ float g_csum[B*H*CH*D];     // per-chunk column sums

// ---------------- threefry2x32-20 (jax partitionable path) ----------------
__device__ __forceinline__ uint32_t rotl32(uint32_t x, int r) {
    return (x << r) | (x >> (32 - r));
}

__device__ __forceinline__ void threefry2x32(uint32_t k0, uint32_t k1,
                                             uint32_t x0, uint32_t x1,
                                             uint32_t& o0, uint32_t& o1) {
    uint32_t ks2 = k0 ^ k1 ^ 0x1BD11BDAu;
    x0 += k0; x1 += k1;
#define TF_R(R) { x0 += x1; x1 = rotl32(x1, (R)); x1 ^= x0; }
    TF_R(13) TF_R(15) TF_R(26) TF_R(6)
    x0 += k1;  x1 += ks2 + 1u;
    TF_R(17) TF_R(29) TF_R(16) TF_R(24)
    x0 += ks2; x1 += k0 + 2u;
    TF_R(13) TF_R(15) TF_R(26) TF_R(6)
    x0 += k0;  x1 += k1 + 3u;
    TF_R(17) TF_R(29) TF_R(16) TF_R(24)
    x0 += k1;  x1 += ks2 + 4u;
    TF_R(13) TF_R(15) TF_R(26) TF_R(6)
    x0 += ks2; x1 += k0 + 5u;
#undef TF_R
    o0 = x0; o1 = x1;
}

__global__ void k_genidx() {
    int t = blockIdx.x * blockDim.x + threadIdx.x;
    if (t >= NIDX) return;
    uint32_t c0, c1;
    threefry2x32(0u, 42u, 0u, 1u, c0, c1);   // lower key (constant-folds)
    uint32_t o0, o1;
    threefry2x32(c0, c1, 0u, (uint32_t)t, o0, o1);
    g_idx[t] = (int)((o0 ^ o1) & (uint32_t)(L - 1));
}

// ---------------- M metric: warp per query, 4 samples per iteration ----------------
// Lane layout: s = lane>>3 (sample group 0..3), c = lane&7 (8-float chunk of D)
__global__ void k_M(const float* __restrict__ Q, const float* __restrict__ K) {
    int bh = blockIdx.x;
    int b = bh >> 3, h = bh & 7;
    int w = threadIdx.x >> 5, l = threadIdx.x & 31;
    int q = blockIdx.y * 8 + w;
    int s = l >> 3, c = l & 7;

    const float4* qr = (const float4*)(Q + (((size_t)b * L + q) * H + h) * D);
    float4 qa = qr[2 * c], qb = qr[2 * c + 1];
    const float4* Kb = (const float4*)(K + (((size_t)b * L) * H + h) * D);

    float mx = -1e30f, sm = 0.f;
    const int* ip = &g_idx[q * SK];
    #pragma unroll 2
    for (int j0 = 0; j0 < 40; j0 += 4) {
        int j = j0 + s;
        int jc = min(j, SK - 1);
        int k = ip[jc];
        const float4* kr = Kb + (size_t)k * (H * D / 4) + 2 * c;
        float4 ka = kr[0], kb = kr[1];
        float p = ka.x * qa.x + ka.y * qa.y + ka.z * qa.z + ka.w * qa.w
                + kb.x * qb.x + kb.y * qb.y + kb.z * qb.z + kb.w * qb.w;
        p += __shfl_xor_sync(0xffffffffu, p, 1);
        p += __shfl_xor_sync(0xffffffffu, p, 2);
        p += __shfl_xor_sync(0xffffffffu, p, 4);
        bool valid = (j < SK);
        mx = fmaxf(mx, valid ? p : -1e30f);
        sm += valid ? p : 0.f;
    }
    // cross-group (4 groups) reduce
    mx = fmaxf(mx, __shfl_xor_sync(0xffffffffu, mx, 8));
    sm += __shfl_xor_sync(0xffffffffu, sm, 8);
    mx = fmaxf(mx, __shfl_xor_sync(0xffffffffu, mx, 16));
    sm += __shfl_xor_sync(0xffffffffu, sm, 16);
    if (l == 0) g_M[bh * L + q] = mx - sm * (1.0f / (float)L);
}

// ---------------- top-38 per (b,h): iterated argmax, warp-shuffle reduce ----------------
__global__ void k_topk() {
    int bh = blockIdx.x;
    __shared__ float vals[L];
    __shared__ float wv[8];
    __shared__ int   wi[8];
    int tid = threadIdx.x;
    int w = tid >> 5, lane = tid & 31;
    for (int i = tid; i < L; i += 256) vals[i] = g_M[bh * L + i];
    __syncthreads();
    for (int t = 0; t < NT; t++) {
        float bv = -1e38f; int bi = L;
        #pragma unroll
        for (int rep = 0; rep < L / 256; rep++) {
            int i = tid + rep * 256;
            float v = vals[i];
            if (v > bv || (v == bv && i < bi)) { bv = v; bi = i; }
        }
        #pragma unroll
        for (int off = 16; off; off >>= 1) {
            float ov = __shfl_down_sync(0xffffffffu, bv, off);
            int   oi = __shfl_down_sync(0xffffffffu, bi, off);
            if (ov > bv || (ov == bv && oi < bi)) { bv = ov; bi = oi; }
        }
        if (lane == 0) { wv[w] = bv; wi[w] = bi; }
        __syncthreads();
        if (tid == 0) {
            float fv = wv[0]; int fi = wi[0];
            #pragma unroll
            for (int ww = 1; ww < 8; ww++)
                if (wv[ww] > fv || (wv[ww] == fv && wi[ww] < fi)) { fv = wv[ww]; fi = wi[ww]; }
            g_top[bh * NT + t] = fi;
            vals[fi] = -1e38f;
        }
        __syncthreads();
    }
}

// ---------------- cumsum pass 1: per-chunk column sums ----------------
__global__ void k_csum_partial(const float* __restrict__ V) {
    int bh = blockIdx.x, chunk = blockIdx.y;
    int b = bh >> 3, h = bh & 7;
    int tid = threadIdx.x;
    int c = tid & 63, r0 = tid >> 6;   // 4 row groups of 32 rows
    float s = 0.f;
    for (int r = r0; r < CROWS; r += 4)
        s += V[(((size_t)b * L + chunk * CROWS + r) * H + h) * D + c];
    __shared__ float red[256];
    red[tid] = s;
    __syncthreads();
    if (tid < 64)
        g_csum[((size_t)bh * CH + chunk) * D + c] =
            red[tid] + red[tid + 64] + red[tid + 128] + red[tid + 192];
}

// ---------------- cumsum pass 2: scan within chunk + chunk-prefix offset ----------------
__global__ void k_csum_scan(const float* __restrict__ V, float* __restrict__ out) {
    int bh = blockIdx.x, chunk = blockIdx.y;
    int b = bh >> 3, h = bh & 7;
    __shared__ float tile[CROWS * 64];
    __shared__ float gsum[8 * 64];
    __shared__ float sbase[64];
    int tid = threadIdx.x;
    int c = tid & 63, g = tid >> 6;    // 8 groups x 16 rows

    if (tid < 64) {
        float s = 0.f;
        for (int cc = 0; cc < chunk; cc++)
            s += g_csum[((size_t)bh * CH + cc) * D + tid];
        sbase[tid] = s;
    }
    int r0 = chunk * CROWS;
    for (int i = tid; i < CROWS * 64; i += 512) {
        int r = i >> 6, cc = i & 63;
        tile[i] = V[(((size_t)b * L + r0 + r) * H + h) * D + cc];
    }
    __syncthreads();

    float s = 0.f;
    int rb = g * 16;
    #pragma unroll
    for (int r = 0; r < 16; r++) {
        s += tile[(rb + r) * 64 + c];
        tile[(rb + r) * 64 + c] = s;
    }
    gsum[g * 64 + c] = s;
    __syncthreads();

    float prefix = sbase[c];
    for (int gg = 0; gg < g; gg++) prefix += gsum[gg * 64 + c];
    #pragma unroll
    for (int r = 0; r < 16; r++)
        out[(((size_t)b * L + r0 + rb + r) * H + h) * D + c] =
            tile[(rb + r) * 64 + c] + prefix;
}

// ---------------- causal attention for selected queries ----------------
// One block per selected query; 8 warps x 4 lane-groups = 32 keys per iteration.
// Lane: s = lane>>3 (key group), c = lane&7 (8-float chunk of D).
__global__ void k_attn(const float* __restrict__ Q, const float* __restrict__ K,
                       const float* __restrict__ V, float* __restrict__ out) {
    int u = blockIdx.x;
    int bh = u / NT, sidx = u % NT;
    int b = bh >> 3, h = bh & 7;
    int q = g_top[bh * NT + sidx];
    int w = threadIdx.x >> 5, l = threadIdx.x & 31;
    int s = l >> 3, c = l & 7;
    const float scale = 0.125f;  // 1/sqrt(64)

    const float4* qr = (const float4*)(Q + (((size_t)b * L + q) * H + h) * D);
    float4 qa = qr[2 * c], qb = qr[2 * c + 1];
    const float4* Kb = (const float4*)(K + (((size_t)b * L) * H + h) * D);
    const float4* Vb = (const float4*)(V + (((size_t)b * L) * H + h) * D);
    const int RS = H * D / 4;  // row stride in float4

    float m = -1e30f, lsum = 0.f;
    float4 acc0 = make_float4(0.f, 0.f, 0.f, 0.f);
    float4 acc1 = make_float4(0.f, 0.f, 0.f, 0.f);

    int n_it = (q + 32) >> 5;
    for (int i = 0; i < n_it; i++) {
        int k = i * 32 + w * 4 + s;
        int kc = min(k, L - 1);
        const float4* kr = Kb + (size_t)kc * RS + 2 * c;
        float4 ka = kr[0], kb = kr[1];
        const float4* vr = Vb + (size_t)kc * RS + 2 * c;
        float4 va = vr[0], vb = vr[1];
        float p = ka.x * qa.x + ka.y * qa.y + ka.z * qa.z + ka.w * qa.w
                + kb.x * qb.x + kb.y * qb.y + kb.z * qb.z + kb.w * qb.w;
        p += __shfl_xor_sync(0xffffffffu, p, 1);
        p += __shfl_xor_sync(0xffffffffu, p, 2);
        p += __shfl_xor_sync(0xffffffffu, p, 4);
        float sc = (k <= q) ? p * scale : -1e30f;
        float mn = fmaxf(m, sc);
        float alpha = __expf(m - mn);
        float pe    = __expf(sc - mn);
        lsum = lsum * alpha + pe;
        acc0.x = acc0.x * alpha + pe * va.x;
        acc0.y = acc0.y * alpha + pe * va.y;
        acc0.z = acc0.z * alpha + pe * va.z;
        acc0.w = acc0.w * alpha + pe * va.w;
        acc1.x = acc1.x * alpha + pe * vb.x;
        acc1.y = acc1.y * alpha + pe * vb.y;
        acc1.z = acc1.z * alpha + pe * vb.z;
        acc1.w = acc1.w * alpha + pe * vb.w;
        m = mn;
    }

    // cross-group flash merge within warp (4 groups -> 1), strides 8 and 16
    float a[8] = {acc0.x, acc0.y, acc0.z, acc0.w, acc1.x, acc1.y, acc1.z, acc1.w};
    #pragma unroll
    for (int off = 8; off <= 16; off <<= 1) {
        float mo = __shfl_xor_sync(0xffffffffu, m, off);
        float lo = __shfl_xor_sync(0xffffffffu, lsum, off);
        float ao[8];
        #pragma unroll
        for (int i = 0; i < 8; i++) ao[i] = __shfl_xor_sync(0xffffffffu, a[i], off);
        float mn = fmaxf(m, mo);
        float fa = __expf(m - mn), fb = __expf(mo - mn);
        lsum = lsum * fa + lo * fb;
        #pragma unroll
        for (int i = 0; i < 8; i++) a[i] = a[i] * fa + ao[i] * fb;
        m = mn;
    }

    // cross-warp merge via shared
    __shared__ float sm_[8], sl_[8], sacc[8][64];
    if (l == 0) { sm_[w] = m; sl_[w] = lsum; }
    if (l < 8) {
        #pragma unroll
        for (int i = 0; i < 8; i++) sacc[w][c * 8 + i] = a[i];
    }
    __syncthreads();

    if (threadIdx.x < 64) {
        int d = threadIdx.x;
        float gm = -1e30f;
        #pragma unroll
        for (int ww = 0; ww < 8; ww++)
            if (sl_[ww] > 0.f) gm = fmaxf(gm, sm_[ww]);
        float den = 0.f, num = 0.f;
        #pragma unroll
        for (int ww = 0; ww < 8; ww++) {
            if (sl_[ww] > 0.f) {
                float f = __expf(sm_[ww] - gm);
                den += f * sl_[ww];
                num += f * sacc[ww][d];
            }
        }
        out[(((size_t)b * L + q) * H + h) * D + d] = num / den;
    }
}

// ---------------- launch ----------------
extern "C" void kernel_launch(void* const* d_in, const int* in_sizes, int n_in,
                              void* d_out, int out_size) {
    (void)in_sizes; (void)n_in; (void)out_size;
    const float* Q = (const float*)d_in[0];
    const float* K = (const float*)d_in[1];
    const float* V = (const float*)d_in[2];
    float* out = (float*)d_out;

    k_genidx<<<(NIDX + 255) / 256, 256>>>();
    k_M<<<dim3(B * H, L / 8), 256>>>(Q, K);
    k_topk<<<B * H, 256>>>();
    k_csum_partial<<<dim3(B * H, CH), 256>>>(V);
    k_csum_scan<<<dim3(B * H, CH), 512>>>(V, out);
    k_attn<<<B * H * NT, 256>>>(Q, K, V, out);
}